// round 1
// baseline (speedup 1.0000x reference)
#include <cuda_runtime.h>

#define MAXN 100000
#define MAXE 1600000
#define HIDC 64
#define NB 64

// ---------------- device scratch (no allocations allowed) ----------------
__device__ __align__(16) int   g_deg[MAXN];
__device__ __align__(16) int   g_off[MAXN + 1];
__device__ __align__(16) int   g_cur[MAXN];
__device__ __align__(16) int   g_srcidx[MAXE];
__device__ __align__(16) int   g_part[1024];
__device__ __align__(16) float g_h[MAXN * HIDC];
__device__ __align__(16) float g_y[MAXN * HIDC];
__device__ __align__(16) float g_agg[MAXN * HIDC];
__device__ __align__(16) float g_agg6[MAXN * 8];
__device__ __align__(16) float g_stats[3 * 2 * HIDC];
__device__ __align__(16) float g_scale[HIDC];
__device__ __align__(16) float g_shift[HIDC];
__device__ float g_sumexp;
__device__ __align__(16) float g_pool[NB * HIDC];
__device__ int   g_bcnt[NB];
__device__ int   g_is64;

// ---------------- dtype detection (int64 vs int32 indices) ----------------
__global__ void k_detect(const long long* __restrict__ ei, int n) {
    if (threadIdx.x == 0 && blockIdx.x == 0) {
        int is64 = 1;
        for (int i = 0; i < 512; i++) {
            long long v = ei[i];
            if (v < 0 || v >= (long long)n) { is64 = 0; break; }
        }
        g_is64 = is64;
    }
}

__device__ __forceinline__ int load_idx(const void* p, int i) {
    if (g_is64) return (int)((const long long*)p)[i];
    return ((const int*)p)[i];
}

// ---------------- init ----------------
__global__ void k_zero(int n) {
    int i = blockIdx.x * blockDim.x + threadIdx.x;
    if (i < n) g_deg[i] = 0;
    if (i < 3 * 2 * HIDC) g_stats[i] = 0.f;
    if (i < NB * HIDC) g_pool[i] = 0.f;
    if (i < NB) g_bcnt[i] = 0;
    if (i == 0) g_sumexp = 0.f;
}

// ---------------- CSR build ----------------
__global__ void k_hist(const void* __restrict__ ei, int e) {
    int i = blockIdx.x * blockDim.x + threadIdx.x;
    if (i >= e) return;
    int dst = load_idx(ei, e + i);
    atomicAdd(&g_deg[dst], 1);
}

__global__ void k_scan1(int n) {
    __shared__ int sh[1024];
    int t = threadIdx.x;
    int i = blockIdx.x * 1024 + t;
    int v = (i < n) ? g_deg[i] : 0;
    sh[t] = v; __syncthreads();
    for (int d = 512; d > 0; d >>= 1) {
        if (t < d) sh[t] += sh[t + d];
        __syncthreads();
    }
    if (t == 0) g_part[blockIdx.x] = sh[0];
}

__global__ void k_scan2(int nb, int n, int e) {
    __shared__ int sh[1024];
    int t = threadIdx.x;
    int v = (t < nb) ? g_part[t] : 0;
    sh[t] = v; __syncthreads();
    for (int d = 1; d < 1024; d <<= 1) {
        int add = (t >= d) ? sh[t - d] : 0;
        __syncthreads();
        sh[t] += add;
        __syncthreads();
    }
    if (t < nb) g_part[t] = sh[t] - v;     // exclusive block offsets
    if (t == 0) g_off[n] = e;
}

__global__ void k_scan3(int n) {
    __shared__ int sh[1024];
    int t = threadIdx.x;
    int i = blockIdx.x * 1024 + t;
    int v = (i < n) ? g_deg[i] : 0;
    sh[t] = v; __syncthreads();
    for (int d = 1; d < 1024; d <<= 1) {
        int add = (t >= d) ? sh[t - d] : 0;
        __syncthreads();
        sh[t] += add;
        __syncthreads();
    }
    int excl = sh[t] - v + g_part[blockIdx.x];
    if (i < n) { g_off[i] = excl; g_cur[i] = excl; }
}

__global__ void k_scatter(const void* __restrict__ ei, int e) {
    int i = blockIdx.x * blockDim.x + threadIdx.x;
    if (i >= e) return;
    int src = load_idx(ei, i);
    int dst = load_idx(ei, e + i);
    int pos = atomicAdd(&g_cur[dst], 1);
    g_srcidx[pos] = src;
}

// ---------------- aggregation ----------------
// layer 1: 6-channel gather, one warp per node, lanes 0..5 = channels
__global__ void k_agg6(const float* __restrict__ x, int n) {
    int w = (blockIdx.x * blockDim.x + threadIdx.x) >> 5;
    int lane = threadIdx.x & 31;
    if (w >= n) return;
    int s = g_off[w], t = g_off[w + 1];
    float acc = 0.f;
    for (int e = s; e < t; e++) {
        int src = __ldg(&g_srcidx[e]);
        if (lane < 6) acc += __ldg(&x[src * 6 + lane]);
    }
    float inv = 1.f / fmaxf((float)(t - s), 1.f);
    if (lane < 8) g_agg6[w * 8 + lane] = (lane < 6) ? acc * inv : 0.f;
}

// layers 2/3: 64-channel gather, one warp per node, lane = 2 channels (float2)
__global__ void k_agg64(const float* __restrict__ hin, int n) {
    int w = (blockIdx.x * blockDim.x + threadIdx.x) >> 5;
    int lane = threadIdx.x & 31;
    if (w >= n) return;
    int s = g_off[w], t = g_off[w + 1];
    float ax = 0.f, ay = 0.f;
    const float2* hp = (const float2*)hin;
    for (int e = s; e < t; e++) {
        int src = __ldg(&g_srcidx[e]);
        float2 v = __ldg(&hp[src * 32 + lane]);
        ax += v.x; ay += v.y;
    }
    float inv = 1.f / fmaxf((float)(t - s), 1.f);
    float2 o; o.x = ax * inv; o.y = ay * inv;
    ((float2*)g_agg)[w * 32 + lane] = o;
}

// ---------------- per-node dense matmul + BN-stats ----------------
// y = agg @ Wl + h @ Wr + b ; accumulate per-channel sum/sumsq
// Each warp: 8 nodes x 64 channels (lane owns channels 2c,2c+1). Block = 8 warps = 64 nodes.
template <int DIN, int SA, int SH>
__global__ void __launch_bounds__(256)
k_mm(const float* __restrict__ aggin, const float* __restrict__ hin,
     const float* __restrict__ Wl, const float* __restrict__ Wr,
     const float* __restrict__ bias, float* __restrict__ stats, int n) {
    __shared__ float sWl[DIN * 64];
    __shared__ float sWr[DIN * 64];
    __shared__ float sb[64];
    __shared__ float redS[8][64];
    __shared__ float redQ[8][64];
    int tid = threadIdx.x;
    for (int i = tid; i < DIN * 64; i += 256) { sWl[i] = Wl[i]; sWr[i] = Wr[i]; }
    if (tid < 64) sb[tid] = bias[tid];
    __syncthreads();

    int warp = tid >> 5, lane = tid & 31;
    int c0 = lane * 2;
    int base = (blockIdx.x * 8 + warp) * 8;

    float y[8][2];
#pragma unroll
    for (int j = 0; j < 8; j++) { y[j][0] = sb[c0]; y[j][1] = sb[c0 + 1]; }

    if (DIN == 64) {
#pragma unroll 4
        for (int k = 0; k < 64; k += 4) {
            float2 wl0 = *(float2*)&sWl[(k + 0) * 64 + c0];
            float2 wl1 = *(float2*)&sWl[(k + 1) * 64 + c0];
            float2 wl2 = *(float2*)&sWl[(k + 2) * 64 + c0];
            float2 wl3 = *(float2*)&sWl[(k + 3) * 64 + c0];
            float2 wr0 = *(float2*)&sWr[(k + 0) * 64 + c0];
            float2 wr1 = *(float2*)&sWr[(k + 1) * 64 + c0];
            float2 wr2 = *(float2*)&sWr[(k + 2) * 64 + c0];
            float2 wr3 = *(float2*)&sWr[(k + 3) * 64 + c0];
#pragma unroll
            for (int j = 0; j < 8; j++) {
                int node = base + j; if (node >= n) node = n - 1;
                float4 a = *(const float4*)&aggin[node * SA + k];
                float4 h = *(const float4*)&hin[node * SH + k];
                y[j][0] += a.x * wl0.x + a.y * wl1.x + a.z * wl2.x + a.w * wl3.x
                         + h.x * wr0.x + h.y * wr1.x + h.z * wr2.x + h.w * wr3.x;
                y[j][1] += a.x * wl0.y + a.y * wl1.y + a.z * wl2.y + a.w * wl3.y
                         + h.x * wr0.y + h.y * wr1.y + h.z * wr2.y + h.w * wr3.y;
            }
        }
    } else {
#pragma unroll
        for (int k = 0; k < DIN; k++) {
            float2 wl = *(float2*)&sWl[k * 64 + c0];
            float2 wr = *(float2*)&sWr[k * 64 + c0];
#pragma unroll
            for (int j = 0; j < 8; j++) {
                int node = base + j; if (node >= n) node = n - 1;
                float a = __ldg(&aggin[node * SA + k]);
                float h = __ldg(&hin[node * SH + k]);
                y[j][0] += a * wl.x + h * wr.x;
                y[j][1] += a * wl.y + h * wr.y;
            }
        }
    }

    float ls0 = 0.f, ls1 = 0.f, lq0 = 0.f, lq1 = 0.f;
#pragma unroll
    for (int j = 0; j < 8; j++) {
        int node = base + j;
        if (node < n) {
            float v0 = y[j][0], v1 = y[j][1];
            float2 o; o.x = v0; o.y = v1;
            *(float2*)&g_y[node * 64 + c0] = o;
            ls0 += v0; lq0 += v0 * v0;
            ls1 += v1; lq1 += v1 * v1;
        }
    }
    redS[warp][c0] = ls0; redS[warp][c0 + 1] = ls1;
    redQ[warp][c0] = lq0; redQ[warp][c0 + 1] = lq1;
    __syncthreads();
    if (tid < 64) {
        float s = 0.f, q = 0.f;
#pragma unroll
        for (int w2 = 0; w2 < 8; w2++) { s += redS[w2][tid]; q += redQ[w2][tid]; }
        atomicAdd(&stats[tid], s);
        atomicAdd(&stats[64 + tid], q);
    }
}

// ---------------- BN finalize + apply ----------------
__global__ void k_bnfin(const float* __restrict__ stats,
                        const float* __restrict__ g, const float* __restrict__ be,
                        float invn) {
    int c = threadIdx.x;
    float mu = stats[c] * invn;
    float var = stats[64 + c] * invn - mu * mu;
    float rstd = rsqrtf(var + 1e-5f);
    float sc = rstd * g[c];
    g_scale[c] = sc;
    g_shift[c] = be[c] - mu * sc;
}

__global__ void k_bnapply(int n) {
    int i = blockIdx.x * blockDim.x + threadIdx.x;  // over n*16 float4s
    if (i >= n * 16) return;
    float4 v = *(const float4*)&g_y[i * 4];
    int c = (i & 15) * 4;
    float4 sc = *(const float4*)&g_scale[c];
    float4 sh = *(const float4*)&g_shift[c];
    v.x = fmaxf(v.x * sc.x + sh.x, 0.f);
    v.y = fmaxf(v.y * sc.y + sh.y, 0.f);
    v.z = fmaxf(v.z * sc.z + sh.z, 0.f);
    v.w = fmaxf(v.w * sc.w + sh.w, 0.f);
    *(float4*)&g_h[i * 4] = v;
}

// ---------------- pooling ----------------
__global__ void k_prepool(const float* __restrict__ x, const void* __restrict__ batch, int n) {
    __shared__ float ssum[256];
    __shared__ int hist[64];
    int tid = threadIdx.x;
    if (tid < 64) hist[tid] = 0;
    __syncthreads();
    int i = blockIdx.x * blockDim.x + tid;
    float loc = 0.f;
    if (i < n) {
        loc = expf(__ldg(&x[i * 6 + 4]));
        atomicAdd(&hist[load_idx(batch, i)], 1);
    }
    ssum[tid] = loc; __syncthreads();
    for (int d = 128; d > 0; d >>= 1) {
        if (tid < d) ssum[tid] += ssum[tid + d];
        __syncthreads();
    }
    if (tid == 0) atomicAdd(&g_sumexp, ssum[0]);
    if (tid < 64 && hist[tid]) atomicAdd(&g_bcnt[tid], hist[tid]);
}

// batch is sorted: per-block segmented accumulation, 64 threads = 64 channels, 256 nodes/block
__global__ void k_pool(const void* __restrict__ batch, const float* __restrict__ x, int n) {
    __shared__ float w[256];
    __shared__ int bb[256];
    int tid = threadIdx.x;
    int base = blockIdx.x * 256;
    float S = g_sumexp;
    for (int j = tid; j < 256; j += 64) {
        int i = base + j;
        if (i < n) { w[j] = expf(__ldg(&x[i * 6 + 4])) / S; bb[j] = load_idx(batch, i); }
        else { w[j] = 0.f; bb[j] = -1; }
    }
    __syncthreads();
    int m = n - base; if (m > 256) m = 256;
    float acc = 0.f;
    int cur = bb[0];
    for (int j = 0; j < m; j++) {
        int b = bb[j];
        if (b != cur) {
            if (cur >= 0) atomicAdd(&g_pool[cur * 64 + tid], acc);
            acc = 0.f; cur = b;
        }
        acc += w[j] * g_h[(base + j) * 64 + tid];
    }
    if (cur >= 0 && m > 0) atomicAdd(&g_pool[cur * 64 + tid], acc);
}

// ---------------- heads ----------------
__global__ void k_head(const float* __restrict__ phW1, const float* __restrict__ phb1,
                       const float* __restrict__ phW2, const float* __restrict__ phb2,
                       const float* __restrict__ trW1, const float* __restrict__ trb1,
                       const float* __restrict__ trW2, const float* __restrict__ trb2,
                       float* __restrict__ out) {
    __shared__ float pool[64 * 64];
    __shared__ float hid[64 * 32];
    __shared__ float hidt[64 * 16];
    int tid = threadIdx.x;
    for (int i = tid; i < 64 * 64; i += 256) {
        int b = i >> 6;
        float c = (float)g_bcnt[b];
        pool[i] = g_pool[i] / fmaxf(c, 1.f);
    }
    __syncthreads();
    for (int i = tid; i < 64 * 32; i += 256) {
        int b = i >> 5, j = i & 31;
        float s = phb1[j];
        for (int k = 0; k < 64; k++) s += pool[b * 64 + k] * phW1[k * 32 + j];
        hid[i] = fmaxf(s, 0.f);
    }
    for (int i = tid; i < 64 * 16; i += 256) {
        int b = i >> 4, j = i & 15;
        float s = trb1[j];
        for (int k = 0; k < 64; k++) s += pool[b * 64 + k] * trW1[k * 16 + j];
        hidt[i] = fmaxf(s, 0.f);
    }
    __syncthreads();
    for (int i = tid; i < 64 * 3; i += 256) {
        int b = i / 3, j = i - b * 3;
        float s = phb2[j];
        for (int k = 0; k < 32; k++) s += hid[b * 32 + k] * phW2[k * 3 + j];
        out[i] = s;
    }
    for (int i = tid; i < 64; i += 256) {
        float s = trb2[0];
        for (int k = 0; k < 16; k++) s += hidt[i * 16 + k] * trW2[k];
        out[192 + i] = 1.f / (1.f + expf(-s));
    }
}

// ---------------- launch ----------------
extern "C" void kernel_launch(void* const* d_in, const int* in_sizes, int n_in,
                              void* d_out, int out_size) {
    const float* x   = (const float*)d_in[0];
    const void*  ei  = d_in[1];
    const void*  bat = d_in[2];
    const float* W1l = (const float*)d_in[3];
    const float* b1  = (const float*)d_in[4];
    const float* W1r = (const float*)d_in[5];
    const float* W2l = (const float*)d_in[6];
    const float* b2  = (const float*)d_in[7];
    const float* W2r = (const float*)d_in[8];
    const float* W3l = (const float*)d_in[9];
    const float* b3  = (const float*)d_in[10];
    const float* W3r = (const float*)d_in[11];
    const float* g1  = (const float*)d_in[12];
    const float* be1 = (const float*)d_in[13];
    const float* g2  = (const float*)d_in[14];
    const float* be2 = (const float*)d_in[15];
    const float* g3  = (const float*)d_in[16];
    const float* be3 = (const float*)d_in[17];
    const float* phW1 = (const float*)d_in[18];
    const float* phb1 = (const float*)d_in[19];
    const float* phW2 = (const float*)d_in[20];
    const float* phb2 = (const float*)d_in[21];
    const float* trW1 = (const float*)d_in[22];
    const float* trb1 = (const float*)d_in[23];
    const float* trW2 = (const float*)d_in[24];
    const float* trb2 = (const float*)d_in[25];
    float* out = (float*)d_out;

    int n = in_sizes[0] / 6;
    int e = in_sizes[1] / 2;

    float *p_agg, *p_agg6, *p_h, *p_stats;
    cudaGetSymbolAddress((void**)&p_agg, g_agg);
    cudaGetSymbolAddress((void**)&p_agg6, g_agg6);
    cudaGetSymbolAddress((void**)&p_h, g_h);
    cudaGetSymbolAddress((void**)&p_stats, g_stats);

    // dtype detection + init + CSR build
    k_detect<<<1, 32>>>((const long long*)ei, n);
    k_zero<<<(n + 255) / 256, 256>>>(n);
    k_hist<<<(e + 255) / 256, 256>>>(ei, e);
    int nb = (n + 1023) / 1024;
    k_scan1<<<nb, 1024>>>(n);
    k_scan2<<<1, 1024>>>(nb, n, e);
    k_scan3<<<nb, 1024>>>(n);
    k_scatter<<<(e + 255) / 256, 256>>>(ei, e);

    int aggBlocks = (n * 32 + 255) / 256;
    int mmBlocks = (n + 63) / 64;
    int bnBlocks = (n * 16 + 255) / 256;

    // ----- layer 1 -----
    k_agg6<<<aggBlocks, 256>>>(x, n);
    k_mm<6, 8, 6><<<mmBlocks, 256>>>(p_agg6, x, W1l, W1r, b1, p_stats + 0 * 128, n);
    k_bnfin<<<1, 64>>>(p_stats + 0 * 128, g1, be1, 1.f / (float)n);
    k_bnapply<<<bnBlocks, 256>>>(n);

    // ----- layer 2 -----
    k_agg64<<<aggBlocks, 256>>>(p_h, n);
    k_mm<64, 64, 64><<<mmBlocks, 256>>>(p_agg, p_h, W2l, W2r, b2, p_stats + 1 * 128, n);
    k_bnfin<<<1, 64>>>(p_stats + 1 * 128, g2, be2, 1.f / (float)n);
    k_bnapply<<<bnBlocks, 256>>>(n);

    // ----- layer 3 -----
    k_agg64<<<aggBlocks, 256>>>(p_h, n);
    k_mm<64, 64, 64><<<mmBlocks, 256>>>(p_agg, p_h, W3l, W3r, b3, p_stats + 2 * 128, n);
    k_bnfin<<<1, 64>>>(p_stats + 2 * 128, g3, be3, 1.f / (float)n);
    k_bnapply<<<bnBlocks, 256>>>(n);

    // ----- pooling + heads -----
    k_prepool<<<(n + 255) / 256, 256>>>(x, bat, n);
    k_pool<<<(n + 255) / 256, 64>>>(bat, x, n);
    k_head<<<1, 256>>>(phW1, phb1, phW2, phb2, trW1, trb1, trW2, trb2, out);
}